// round 1
// baseline (speedup 1.0000x reference)
#include <cuda_runtime.h>
#include <cuda_bf16.h>

// SilkNNUE: out[n] = MLP( relu( sum_{t<29} emb[x[n,t]] ) )
// Inputs (metadata order): x[int32 131072x32], emb[f32 7424x128],
//   W2[f32 32x128], b2[f32 32], W3[f32 32x64], b3[f32 32], W4[f32 1x64]
// Output: f32 [131072]

#define WARPS_PER_BLOCK 8
#define SAMPLES_PER_WARP 8
#define THREADS (WARPS_PER_BLOCK * 32)
#define N_SAMPLES 131072
#define SAMPLES_PER_BLOCK (WARPS_PER_BLOCK * SAMPLES_PER_WARP)

__global__ __launch_bounds__(THREADS)
void silk_nnue_kernel(const int* __restrict__ x,
                      const float* __restrict__ emb,
                      const float* __restrict__ W2,
                      const float* __restrict__ b2,
                      const float* __restrict__ W3,
                      const float* __restrict__ b3,
                      const float* __restrict__ W4,
                      float* __restrict__ out)
{
    // Transposed weights in smem for conflict-free lane-indexed reads.
    __shared__ float sW2T[128 * 32];          // sW2T[k*32 + j] = W2[j,k]
    __shared__ float sW3T[64 * 32];           // sW3T[j*32 + i] = W3[i,j]
    __shared__ float sb2[32];
    __shared__ float sb3[32];
    __shared__ float sW4[64];
    __shared__ float sh[WARPS_PER_BLOCK][128]; // per-warp hidden vector

    const int tid = threadIdx.x;

    // Stage weights once per block.
    for (int i = tid; i < 32 * 128; i += THREADS) {
        int j = i >> 7;          // output index 0..31
        int k = i & 127;         // input index 0..127
        sW2T[k * 32 + j] = W2[i];
    }
    for (int i = tid; i < 32 * 64; i += THREADS) {
        int oi = i >> 6;         // output index 0..31
        int j  = i & 63;         // input index 0..63
        sW3T[j * 32 + oi] = W3[i];
    }
    if (tid < 32) { sb2[tid] = b2[tid]; sb3[tid] = b3[tid]; }
    if (tid < 64) { sW4[tid] = W4[tid]; }
    __syncthreads();

    const int warp = tid >> 5;
    const int lane = tid & 31;
    const int base_sample = blockIdx.x * SAMPLES_PER_BLOCK + warp * SAMPLES_PER_WARP;

    float* hrow = sh[warp];

    #pragma unroll 1
    for (int s = 0; s < SAMPLES_PER_WARP; s++) {
        const int sample = base_sample + s;
        const int* xrow = x + (size_t)sample * 32;

        // ---- Layer 1: gather-sum of 29 embedding rows (warp-cooperative) ----
        // lane l accumulates h[4l .. 4l+3]; each LDG.128 across the warp covers
        // a full 512B emb row (coalesced, 4 sectors). Full unroll -> deep MLP.
        float4 acc = make_float4(0.f, 0.f, 0.f, 0.f);
        #pragma unroll
        for (int t = 0; t < 29; t++) {
            const int id = __ldg(&xrow[t]);                  // uniform across warp
            const float4 e = __ldg(reinterpret_cast<const float4*>(
                emb + (size_t)id * 128) + lane);
            acc.x += e.x; acc.y += e.y; acc.z += e.z; acc.w += e.w;
        }
        acc.x = fmaxf(acc.x, 0.f);
        acc.y = fmaxf(acc.y, 0.f);
        acc.z = fmaxf(acc.z, 0.f);
        acc.w = fmaxf(acc.w, 0.f);

        // Publish h to this warp's smem slot.
        __syncwarp();   // previous iteration's readers are done
        reinterpret_cast<float4*>(hrow)[lane] = acc;
        __syncwarp();

        // ---- Layer 2: y[lane] = b2[lane] + sum_k h[k] * W2[lane,k] ----
        float y = sb2[lane];
        #pragma unroll
        for (int k = 0; k < 128; k += 4) {
            // float4 broadcast read (same address across warp): conflict-free
            const float4 hv = *reinterpret_cast<const float4*>(&hrow[k]);
            y = fmaf(hv.x, sW2T[(k + 0) * 32 + lane], y);
            y = fmaf(hv.y, sW2T[(k + 1) * 32 + lane], y);
            y = fmaf(hv.z, sW2T[(k + 2) * 32 + lane], y);
            y = fmaf(hv.w, sW2T[(k + 3) * 32 + lane], y);
        }

        // ---- Layer 3: CReLU(y) -> 64, dot with W3 rows. y broadcast via shfl ----
        float a3 = sb3[lane];
        #pragma unroll
        for (int j = 0; j < 32; j++) {
            const float t = __shfl_sync(0xffffffffu, y, j);
            a3 = fmaf(fmaxf(t, 0.f),  sW3T[j * 32 + lane], a3);
            a3 = fmaf(fmaxf(-t, 0.f), sW3T[(j + 32) * 32 + lane], a3);
        }

        // ---- Layer 4: CReLU(a3) -> 64, dot with W4, warp-reduce ----
        float contrib = fmaxf(a3, 0.f) * sW4[lane]
                      + fmaxf(-a3, 0.f) * sW4[32 + lane];
        #pragma unroll
        for (int o = 16; o > 0; o >>= 1)
            contrib += __shfl_xor_sync(0xffffffffu, contrib, o);

        if (lane == 0) out[sample] = contrib;
    }
}

extern "C" void kernel_launch(void* const* d_in, const int* in_sizes, int n_in,
                              void* d_out, int out_size)
{
    const int*   x   = (const int*)  d_in[0];
    const float* emb = (const float*)d_in[1];
    const float* W2  = (const float*)d_in[2];
    const float* b2  = (const float*)d_in[3];
    const float* W3  = (const float*)d_in[4];
    const float* b3  = (const float*)d_in[5];
    const float* W4  = (const float*)d_in[6];
    float* out = (float*)d_out;

    const int grid = N_SAMPLES / SAMPLES_PER_BLOCK;  // 131072/64 = 2048
    silk_nnue_kernel<<<grid, THREADS>>>(x, emb, W2, b2, W3, b3, W4, out);
}

// round 5
// speedup vs baseline: 1.3632x; 1.3632x over previous
#include <cuda_runtime.h>
#include <cuda_bf16.h>

// SilkNNUE: out[n] = MLP( relu( sum_{t<29} emb[x[n,t]] ) )
// Inputs (metadata order): x[int32 131072x32], emb[f32 7424x128],
//   W2[f32 32x128], b2[f32 32], W3[f32 32x64], b3[f32 32], W4[f32 1x64]
// Output: f32 [131072]

#define WARPS_PER_BLOCK 8
#define THREADS (WARPS_PER_BLOCK * 32)
#define SPW 8                                  // samples batched per warp
#define SAMPLES_PER_BLOCK (WARPS_PER_BLOCK * SPW)  // 64
#define N_SAMPLES 131072

__global__ __launch_bounds__(THREADS)
void silk_nnue_kernel(const int* __restrict__ x,
                      const float* __restrict__ emb,
                      const float* __restrict__ W2,
                      const float* __restrict__ b2,
                      const float* __restrict__ W3,
                      const float* __restrict__ b3,
                      const float* __restrict__ W4,
                      float* __restrict__ out)
{
    // Transposed weights for conflict-free lane-indexed LDS.
    __shared__ float  sW2T[128 * 32];                    // sW2T[k*32+j] = W2[j,k]   16KB
    __shared__ float  sW3T[64 * 32];                     // sW3T[j*32+i] = W3[i,j]    8KB
    __shared__ float4 sh4[WARPS_PER_BLOCK][SPW][32];     // hidden h per sample      16KB
    __shared__ float2 spn[WARPS_PER_BLOCK][SPW][32];     // {relu(y), relu(-y)}       2KB

    const int tid = threadIdx.x;

    // Stage weights once per block.
    for (int i = tid; i < 32 * 128; i += THREADS) {
        int j = i >> 7, k = i & 127;
        sW2T[k * 32 + j] = W2[i];
    }
    for (int i = tid; i < 32 * 64; i += THREADS) {
        int oi = i >> 6, j = i & 63;
        sW3T[j * 32 + oi] = W3[i];
    }
    __syncthreads();

    const int warp = tid >> 5;
    const int lane = tid & 31;
    const int base = blockIdx.x * SAMPLES_PER_BLOCK + warp * SPW;

    // Per-lane invariant params (loaded once, kept in registers).
    const float rb2  = b2[lane];
    const float rb3  = b3[lane];
    const float rw4a = W4[lane];
    const float rw4b = W4[32 + lane];

    // ---- Cooperative index load: lane t holds x[base+s, t] ----
    int idxreg[SPW];
    #pragma unroll
    for (int s = 0; s < SPW; s++)
        idxreg[s] = __ldg(&x[(size_t)(base + s) * 32 + lane]);

    // ---- Layer 1: gather-sum, 2 samples interleaved, packed f32x2 adds ----
    // lane l accumulates h[4l..4l+3] for samples s and s+1 concurrently:
    // 58 LDG.128 in flight per pass, halving exposed latency tails.
    #pragma unroll 1
    for (int s = 0; s < SPW; s += 2) {
        unsigned long long a0 = 0ull, a1 = 0ull;   // sample s
        unsigned long long c0 = 0ull, c1 = 0ull;   // sample s+1
        #pragma unroll
        for (int t = 0; t < 29; t++) {
            const int idA = __shfl_sync(0xffffffffu, idxreg[s],     t);
            const int idB = __shfl_sync(0xffffffffu, idxreg[s + 1], t);
            const ulonglong2 vA = __ldg(
                reinterpret_cast<const ulonglong2*>(emb + (size_t)idA * 128) + lane);
            const ulonglong2 vB = __ldg(
                reinterpret_cast<const ulonglong2*>(emb + (size_t)idB * 128) + lane);
            asm("add.rn.f32x2 %0, %1, %2;" : "=l"(a0) : "l"(a0), "l"(vA.x));
            asm("add.rn.f32x2 %0, %1, %2;" : "=l"(a1) : "l"(a1), "l"(vA.y));
            asm("add.rn.f32x2 %0, %1, %2;" : "=l"(c0) : "l"(c0), "l"(vB.x));
            asm("add.rn.f32x2 %0, %1, %2;" : "=l"(c1) : "l"(c1), "l"(vB.y));
        }
        float h0, h1, h2, h3;
        asm("mov.b64 {%0, %1}, %2;" : "=f"(h0), "=f"(h1) : "l"(a0));
        asm("mov.b64 {%0, %1}, %2;" : "=f"(h2), "=f"(h3) : "l"(a1));
        sh4[warp][s][lane] = make_float4(fmaxf(h0, 0.f), fmaxf(h1, 0.f),
                                         fmaxf(h2, 0.f), fmaxf(h3, 0.f));
        asm("mov.b64 {%0, %1}, %2;" : "=f"(h0), "=f"(h1) : "l"(c0));
        asm("mov.b64 {%0, %1}, %2;" : "=f"(h2), "=f"(h3) : "l"(c1));
        sh4[warp][s + 1][lane] = make_float4(fmaxf(h0, 0.f), fmaxf(h1, 0.f),
                                             fmaxf(h2, 0.f), fmaxf(h3, 0.f));
    }
    __syncwarp();

    // ---- Layer 2: y[s][lane] = b2[lane] + sum_k h[s][k]*W2[lane,k] ----
    // Weights loaded ONCE per k-group and reused across all 8 samples.
    float y[SPW];
    #pragma unroll
    for (int s = 0; s < SPW; s++) y[s] = rb2;

    #pragma unroll 4
    for (int g = 0; g < 32; g++) {           // k = 4*g
        const float w0 = sW2T[(4 * g + 0) * 32 + lane];
        const float w1 = sW2T[(4 * g + 1) * 32 + lane];
        const float w2 = sW2T[(4 * g + 2) * 32 + lane];
        const float w3 = sW2T[(4 * g + 3) * 32 + lane];
        #pragma unroll
        for (int s = 0; s < SPW; s++) {
            const float4 hv = sh4[warp][s][g];   // broadcast LDS.128
            y[s] = fmaf(hv.x, w0, y[s]);
            y[s] = fmaf(hv.y, w1, y[s]);
            y[s] = fmaf(hv.z, w2, y[s]);
            y[s] = fmaf(hv.w, w3, y[s]);
        }
    }

    // Precompute CReLU pair once; layer-3 hot loop becomes pure FMA.
    #pragma unroll
    for (int s = 0; s < SPW; s++)
        spn[warp][s][lane] = make_float2(fmaxf(y[s], 0.f), fmaxf(-y[s], 0.f));
    __syncwarp();

    // ---- Layer 3: a3[s][lane] = b3 + sum_j pos[s][j]*W3[lane,j] + neg[s][j]*W3[lane,j+32] ----
    float a3[SPW];
    #pragma unroll
    for (int s = 0; s < SPW; s++) a3[s] = rb3;

    #pragma unroll 4
    for (int j = 0; j < 32; j++) {
        const float w3a = sW3T[j * 32 + lane];
        const float w3b = sW3T[(j + 32) * 32 + lane];
        #pragma unroll
        for (int s = 0; s < SPW; s++) {
            const float2 pn = spn[warp][s][j];   // broadcast LDS.64
            a3[s] = fmaf(pn.x, w3a, a3[s]);
            a3[s] = fmaf(pn.y, w3b, a3[s]);
        }
    }

    // ---- Layer 4 + warp reduce; lane s keeps result of sample s ----
    float res = 0.f;
    #pragma unroll
    for (int s = 0; s < SPW; s++) {
        float c = fmaxf(a3[s], 0.f) * rw4a + fmaxf(-a3[s], 0.f) * rw4b;
        #pragma unroll
        for (int o = 16; o > 0; o >>= 1)
            c += __shfl_xor_sync(0xffffffffu, c, o);
        if (lane == s) res = c;
    }
    if (lane < SPW) out[base + lane] = res;   // one coalesced 32B store per warp
}

extern "C" void kernel_launch(void* const* d_in, const int* in_sizes, int n_in,
                              void* d_out, int out_size)
{
    const int*   x   = (const int*)  d_in[0];
    const float* emb = (const float*)d_in[1];
    const float* W2  = (const float*)d_in[2];
    const float* b2  = (const float*)d_in[3];
    const float* W3  = (const float*)d_in[4];
    const float* b3  = (const float*)d_in[5];
    const float* W4  = (const float*)d_in[6];
    float* out = (float*)d_out;

    const int grid = N_SAMPLES / SAMPLES_PER_BLOCK;   // 2048
    silk_nnue_kernel<<<grid, THREADS>>>(x, emb, W2, b2, W3, b3, W4, out);
}

// round 10
// speedup vs baseline: 1.6773x; 1.2304x over previous
#include <cuda_runtime.h>
#include <cuda_fp16.h>
#include <cuda_bf16.h>

// SilkNNUE: out[n] = MLP( relu( sum_{t<29} emb[x[n,t]] ) )
// Inputs (metadata order): x[int32 131072x32], emb[f32 7424x128],
//   W2[f32 32x128], b2[f32 32], W3[f32 32x64], b3[f32 32], W4[f32 1x64]
// Output: f32 [131072]

#define WARPS_PER_BLOCK 8
#define THREADS (WARPS_PER_BLOCK * 32)
#define SPW 8
#define SAMPLES_PER_BLOCK (WARPS_PER_BLOCK * SPW)   // 64
#define N_SAMPLES 131072
#define EMB_ROWS 7424

// fp16 copy of the embedding table (1.9 MB). __device__ global = allowed scratch.
__device__ __half2 g_emb_h[EMB_ROWS * 64];

// Convert emb fp32 -> fp16 (runs first in the same graph every launch).
__global__ __launch_bounds__(256)
void convert_emb_kernel(const float* __restrict__ emb)
{
    const int i = blockIdx.x * 256 + threadIdx.x;   // over float4s: 7424*32 = 237568
    const float4 v = __ldg(reinterpret_cast<const float4*>(emb) + i);
    const __half2 h0 = __floats2half2_rn(v.x, v.y);
    const __half2 h1 = __floats2half2_rn(v.z, v.w);
    uint2 p;
    p.x = *reinterpret_cast<const unsigned*>(&h0);
    p.y = *reinterpret_cast<const unsigned*>(&h1);
    reinterpret_cast<uint2*>(g_emb_h)[i] = p;
}

__global__ __launch_bounds__(THREADS)
void silk_nnue_kernel(const int* __restrict__ x,
                      const float* __restrict__ W2,
                      const float* __restrict__ b2,
                      const float* __restrict__ W3,
                      const float* __restrict__ b3,
                      const float* __restrict__ W4,
                      float* __restrict__ out)
{
    __shared__ float sW2T[128 * 32];                      // 16KB  sW2T[k*32+j]=W2[j,k]
    __shared__ float sW3T[64 * 32];                       //  8KB  sW3T[j*32+i]=W3[i,j]
    // Per-warp 4KB scratch: holds sh4 (float4[8][32]) during layers 1-2,
    // then reused for spn (float2[8][32]) in layer 3. Total 32KB.
    __shared__ __align__(16) char sscratch[WARPS_PER_BLOCK * 4096];

    const int tid = threadIdx.x;

    for (int i = tid; i < 32 * 128; i += THREADS) {
        int j = i >> 7, k = i & 127;
        sW2T[k * 32 + j] = W2[i];
    }
    for (int i = tid; i < 32 * 64; i += THREADS) {
        int oi = i >> 6, j = i & 63;
        sW3T[j * 32 + oi] = W3[i];
    }
    __syncthreads();

    const int warp = tid >> 5;
    const int lane = tid & 31;
    const int base = blockIdx.x * SAMPLES_PER_BLOCK + warp * SPW;

    float4* sh4w = reinterpret_cast<float4*>(sscratch + warp * 4096);  // [SPW][32]
    float2* spnw = reinterpret_cast<float2*>(sscratch + warp * 4096);  // [SPW][32] (aliased)

    const float rb2  = b2[lane];
    const float rb3  = b3[lane];
    const float rw4a = W4[lane];
    const float rw4b = W4[32 + lane];

    // Cooperative index load: lane t holds x[base+s, t].
    int idxreg[SPW];
    #pragma unroll
    for (int s = 0; s < SPW; s++)
        idxreg[s] = __ldg(&x[(size_t)(base + s) * 32 + lane]);

    // ---- Layer 1: fp16 gather-sum, 2 samples interleaved, fp32 accumulate ----
    // lane l loads halves h[4l..4l+3] (LDG.64, 256B/warp = 2 L1 lines).
    #pragma unroll 1
    for (int s = 0; s < SPW; s += 2) {
        float a0 = 0.f, a1 = 0.f, a2 = 0.f, a3v = 0.f;   // sample s
        float c0 = 0.f, c1 = 0.f, c2 = 0.f, c3 = 0.f;    // sample s+1
        #pragma unroll
        for (int t = 0; t < 29; t++) {
            const int idA = __shfl_sync(0xffffffffu, idxreg[s],     t);
            const int idB = __shfl_sync(0xffffffffu, idxreg[s + 1], t);
            const uint2 vA = __ldg(reinterpret_cast<const uint2*>(
                                   g_emb_h + (size_t)idA * 64) + lane);
            const uint2 vB = __ldg(reinterpret_cast<const uint2*>(
                                   g_emb_h + (size_t)idB * 64) + lane);
            const float2 fA0 = __half22float2(*reinterpret_cast<const __half2*>(&vA.x));
            const float2 fA1 = __half22float2(*reinterpret_cast<const __half2*>(&vA.y));
            const float2 fB0 = __half22float2(*reinterpret_cast<const __half2*>(&vB.x));
            const float2 fB1 = __half22float2(*reinterpret_cast<const __half2*>(&vB.y));
            a0 += fA0.x; a1 += fA0.y; a2 += fA1.x; a3v += fA1.y;
            c0 += fB0.x; c1 += fB0.y; c2 += fB1.x; c3  += fB1.y;
        }
        sh4w[s * 32 + lane] = make_float4(fmaxf(a0, 0.f), fmaxf(a1, 0.f),
                                          fmaxf(a2, 0.f), fmaxf(a3v, 0.f));
        sh4w[(s + 1) * 32 + lane] = make_float4(fmaxf(c0, 0.f), fmaxf(c1, 0.f),
                                                fmaxf(c2, 0.f), fmaxf(c3, 0.f));
    }
    __syncwarp();

    // ---- Layer 2: y[s][lane] = b2[lane] + sum_k h[s][k]*W2[lane,k] ----
    float y[SPW];
    #pragma unroll
    for (int s = 0; s < SPW; s++) y[s] = rb2;

    #pragma unroll 4
    for (int g = 0; g < 32; g++) {
        const float w0 = sW2T[(4 * g + 0) * 32 + lane];
        const float w1 = sW2T[(4 * g + 1) * 32 + lane];
        const float w2 = sW2T[(4 * g + 2) * 32 + lane];
        const float w3 = sW2T[(4 * g + 3) * 32 + lane];
        #pragma unroll
        for (int s = 0; s < SPW; s++) {
            const float4 hv = sh4w[s * 32 + g];   // broadcast LDS.128
            y[s] = fmaf(hv.x, w0, y[s]);
            y[s] = fmaf(hv.y, w1, y[s]);
            y[s] = fmaf(hv.z, w2, y[s]);
            y[s] = fmaf(hv.w, w3, y[s]);
        }
    }
    __syncwarp();   // all lanes done reading sh4w before aliased spn writes

    // CReLU pairs into the reused scratch region.
    #pragma unroll
    for (int s = 0; s < SPW; s++)
        spnw[s * 32 + lane] = make_float2(fmaxf(y[s], 0.f), fmaxf(-y[s], 0.f));
    __syncwarp();

    // ---- Layer 3 ----
    float a3[SPW];
    #pragma unroll
    for (int s = 0; s < SPW; s++) a3[s] = rb3;

    #pragma unroll 4
    for (int j = 0; j < 32; j++) {
        const float w3a = sW3T[j * 32 + lane];
        const float w3b = sW3T[(j + 32) * 32 + lane];
        #pragma unroll
        for (int s = 0; s < SPW; s++) {
            const float2 pn = spnw[s * 32 + j];   // broadcast LDS.64
            a3[s] = fmaf(pn.x, w3a, a3[s]);
            a3[s] = fmaf(pn.y, w3b, a3[s]);
        }
    }

    // ---- Layer 4 + warp reduce ----
    float res = 0.f;
    #pragma unroll
    for (int s = 0; s < SPW; s++) {
        float c = fmaxf(a3[s], 0.f) * rw4a + fmaxf(-a3[s], 0.f) * rw4b;
        #pragma unroll
        for (int o = 16; o > 0; o >>= 1)
            c += __shfl_xor_sync(0xffffffffu, c, o);
        if (lane == s) res = c;
    }
    if (lane < SPW) out[base + lane] = res;
}

extern "C" void kernel_launch(void* const* d_in, const int* in_sizes, int n_in,
                              void* d_out, int out_size)
{
    const int*   x   = (const int*)  d_in[0];
    const float* emb = (const float*)d_in[1];
    const float* W2  = (const float*)d_in[2];
    const float* b2  = (const float*)d_in[3];
    const float* W3  = (const float*)d_in[4];
    const float* b3  = (const float*)d_in[5];
    const float* W4  = (const float*)d_in[6];
    float* out = (float*)d_out;

    // 7424*128 floats = 237568 float4s = 928 blocks * 256 threads
    convert_emb_kernel<<<928, 256>>>(emb);

    const int grid = N_SAMPLES / SAMPLES_PER_BLOCK;   // 2048
    silk_nnue_kernel<<<grid, THREADS>>>(x, W2, b2, W3, b3, W4, out);
}